// round 1
// baseline (speedup 1.0000x reference)
#include <cuda_runtime.h>
#include <cuda_bf16.h>

// Quaternion tensor product: out[b, s_out, e] accumulates Hamilton product of
// quaternions (in0[b,0..3,e], in1[b,0..3,e]) per channel e in [0,128).
// Row layout: 512 floats = 4 segments x 128 channels = 128 float4 (seg stride 32 float4).
//
// Pure HBM-bound: 1.61 GB traffic, ~16 FMA per channel. Strategy: float4
// vectorized, 8 front-batched independent LDG.128 per thread for MLP=8.

__global__ __launch_bounds__(256) void quat_tp_kernel(
    const float4* __restrict__ in0,
    const float4* __restrict__ in1,
    float4* __restrict__ out)
{
    // idx over B * 32 (each thread = one float4 group of channels for one batch)
    unsigned long long idx = (unsigned long long)blockIdx.x * blockDim.x + threadIdx.x;
    // batch = idx >> 5, group = idx & 31
    // base offset in float4 units: batch*128 + group
    unsigned long long base = ((idx >> 5) << 7) | (idx & 31);

    // Front-batch all 8 loads (independent -> MLP=8, DRAM latency hidden)
    float4 a0 = in0[base];
    float4 a1 = in0[base + 32];
    float4 a2 = in0[base + 64];
    float4 a3 = in0[base + 96];
    float4 b0 = in1[base];
    float4 b1 = in1[base + 32];
    float4 b2 = in1[base + 64];
    float4 b3 = in1[base + 96];

    float4 o0, o1, o2, o3;

    // Hamilton product per lane:
    // o0 = a0*b0 - a1*b1 - a2*b2 - a3*b3
    // o1 = a0*b1 + a1*b0 + a2*b3 - a3*b2
    // o2 = a0*b2 - a1*b3 + a2*b0 + a3*b1
    // o3 = a0*b3 + a1*b2 - a2*b1 + a3*b0
    o0.x = a0.x*b0.x - a1.x*b1.x - a2.x*b2.x - a3.x*b3.x;
    o0.y = a0.y*b0.y - a1.y*b1.y - a2.y*b2.y - a3.y*b3.y;
    o0.z = a0.z*b0.z - a1.z*b1.z - a2.z*b2.z - a3.z*b3.z;
    o0.w = a0.w*b0.w - a1.w*b1.w - a2.w*b2.w - a3.w*b3.w;

    o1.x = a0.x*b1.x + a1.x*b0.x + a2.x*b3.x - a3.x*b2.x;
    o1.y = a0.y*b1.y + a1.y*b0.y + a2.y*b3.y - a3.y*b2.y;
    o1.z = a0.z*b1.z + a1.z*b0.z + a2.z*b3.z - a3.z*b2.z;
    o1.w = a0.w*b1.w + a1.w*b0.w + a2.w*b3.w - a3.w*b2.w;

    o2.x = a0.x*b2.x - a1.x*b3.x + a2.x*b0.x + a3.x*b1.x;
    o2.y = a0.y*b2.y - a1.y*b3.y + a2.y*b0.y + a3.y*b1.y;
    o2.z = a0.z*b2.z - a1.z*b3.z + a2.z*b0.z + a3.z*b1.z;
    o2.w = a0.w*b2.w - a1.w*b3.w + a2.w*b0.w + a3.w*b1.w;

    o3.x = a0.x*b3.x + a1.x*b2.x - a2.x*b1.x + a3.x*b0.x;
    o3.y = a0.y*b3.y + a1.y*b2.y - a2.y*b1.y + a3.y*b0.y;
    o3.z = a0.z*b3.z + a1.z*b2.z - a2.z*b1.z + a3.z*b0.z;
    o3.w = a0.w*b3.w + a1.w*b2.w - a2.w*b1.w + a3.w*b0.w;

    out[base]      = o0;
    out[base + 32] = o1;
    out[base + 64] = o2;
    out[base + 96] = o3;
}

extern "C" void kernel_launch(void* const* d_in, const int* in_sizes, int n_in,
                              void* d_out, int out_size) {
    const float4* in0 = (const float4*)d_in[0];
    const float4* in1 = (const float4*)d_in[1];
    float4* out = (float4*)d_out;

    // total float4 groups = B * 128 per row / 4 segments handled per thread
    // threads = B * 32 = (out_size / 4) / 4  = out_size / 16
    unsigned long long threads_total = (unsigned long long)out_size / 16ull;
    int block = 256;
    unsigned long long grid = (threads_total + block - 1) / block;
    quat_tp_kernel<<<(unsigned int)grid, block>>>(in0, in1, out);
}

// round 2
// speedup vs baseline: 1.0076x; 1.0076x over previous
#include <cuda_runtime.h>
#include <cuda_bf16.h>

// Quaternion tensor product, HBM-bound (1.61 GB traffic @ ~7 TB/s).
// R1: 229.8us, DRAM=88.8%. R2 changes: streaming cache hints (__ldcs/__stcs,
// zero reuse so evict-first / streaming is strictly right), early stores to
// shorten accumulator live ranges (reg pressure -> occupancy).

__global__ __launch_bounds__(256) void quat_tp_kernel(
    const float4* __restrict__ in0,
    const float4* __restrict__ in1,
    float4* __restrict__ out)
{
    unsigned long long idx = (unsigned long long)blockIdx.x * blockDim.x + threadIdx.x;
    // batch = idx >> 5, group = idx & 31; base in float4 units = batch*128 + group
    unsigned long long base = ((idx >> 5) << 7) | (idx & 31);

    // Front-batch all 8 independent loads (MLP=8), streaming (evict-first).
    float4 a0 = __ldcs(in0 + base);
    float4 a1 = __ldcs(in0 + base + 32);
    float4 a2 = __ldcs(in0 + base + 64);
    float4 a3 = __ldcs(in0 + base + 96);
    float4 b0 = __ldcs(in1 + base);
    float4 b1 = __ldcs(in1 + base + 32);
    float4 b2 = __ldcs(in1 + base + 64);
    float4 b3 = __ldcs(in1 + base + 96);

    float4 o;

    // o0 = a0*b0 - a1*b1 - a2*b2 - a3*b3
    o.x = a0.x*b0.x - a1.x*b1.x - a2.x*b2.x - a3.x*b3.x;
    o.y = a0.y*b0.y - a1.y*b1.y - a2.y*b2.y - a3.y*b3.y;
    o.z = a0.z*b0.z - a1.z*b1.z - a2.z*b2.z - a3.z*b3.z;
    o.w = a0.w*b0.w - a1.w*b1.w - a2.w*b2.w - a3.w*b3.w;
    __stcs(out + base, o);

    // o1 = a0*b1 + a1*b0 + a2*b3 - a3*b2
    o.x = a0.x*b1.x + a1.x*b0.x + a2.x*b3.x - a3.x*b2.x;
    o.y = a0.y*b1.y + a1.y*b0.y + a2.y*b3.y - a3.y*b2.y;
    o.z = a0.z*b1.z + a1.z*b0.z + a2.z*b3.z - a3.z*b2.z;
    o.w = a0.w*b1.w + a1.w*b0.w + a2.w*b3.w - a3.w*b2.w;
    __stcs(out + base + 32, o);

    // o2 = a0*b2 - a1*b3 + a2*b0 + a3*b1
    o.x = a0.x*b2.x - a1.x*b3.x + a2.x*b0.x + a3.x*b1.x;
    o.y = a0.y*b2.y - a1.y*b3.y + a2.y*b0.y + a3.y*b1.y;
    o.z = a0.z*b2.z - a1.z*b3.z + a2.z*b0.z + a3.z*b1.z;
    o.w = a0.w*b2.w - a1.w*b3.w + a2.w*b0.w + a3.w*b1.w;
    __stcs(out + base + 64, o);

    // o3 = a0*b3 + a1*b2 - a2*b1 + a3*b0
    o.x = a0.x*b3.x + a1.x*b2.x - a2.x*b1.x + a3.x*b0.x;
    o.y = a0.y*b3.y + a1.y*b2.y - a2.y*b1.y + a3.y*b0.y;
    o.z = a0.z*b3.z + a1.z*b2.z - a2.z*b1.z + a3.z*b0.z;
    o.w = a0.w*b3.w + a1.w*b2.w - a2.w*b1.w + a3.w*b0.w;
    __stcs(out + base + 96, o);
}

extern "C" void kernel_launch(void* const* d_in, const int* in_sizes, int n_in,
                              void* d_out, int out_size) {
    const float4* in0 = (const float4*)d_in[0];
    const float4* in1 = (const float4*)d_in[1];
    float4* out = (float4*)d_out;

    unsigned long long threads_total = (unsigned long long)out_size / 16ull;
    int block = 256;
    unsigned long long grid = (threads_total + block - 1) / block;
    quat_tp_kernel<<<(unsigned int)grid, block>>>(in0, in1, out);
}